// round 11
// baseline (speedup 1.0000x reference)
#include <cuda_runtime.h>
#include <cstdint>

// ---------------------------------------------------------------------------
// Problem constants (shapes fixed by the dataset)
// ---------------------------------------------------------------------------
#define MAXN 50048            // >= N=50000
#define MAXE 800000
#define MAXG 512
#define SCAN_CHUNK 4096       // elements per scan block (512 thr * 8)
#define MAXSB ((MAXN + SCAN_CHUNK - 1) / SCAN_CHUNK)

// ---------------------------------------------------------------------------
// Device scratch (static allocation — no cudaMalloc allowed)
// ---------------------------------------------------------------------------
__device__ __align__(16) float g_bufA[(size_t)MAXN * 128]; // GEMM outputs (transformed feats)
__device__ __align__(16) float g_bufB[(size_t)MAXN * 128]; // layer outputs
__device__ int   g_degi[MAXN];
__device__ int   g_rowptr[MAXN + 1];
__device__ int   g_cursor[MAXN];
__device__ int   g_col[MAXE];
__device__ int   g_bsum[MAXSB];
__device__ float g_dis[MAXN];
__device__ __align__(8) float g_als[MAXN * 2];
__device__ __align__(8) float g_ald[MAXN * 2];
__device__ __align__(16) float g_sums[MAXG * 64];
__device__ float g_cnt[MAXG];

// ---------------------------------------------------------------------------
// Side stream + events for fork/join inside graph capture (created once at
// process init; kernel_launch itself performs identical work every call).
// ---------------------------------------------------------------------------
struct SideStream {
    cudaStream_t s;
    cudaEvent_t fork, join;
    SideStream() {
        cudaStreamCreateWithFlags(&s, cudaStreamNonBlocking);
        cudaEventCreateWithFlags(&fork, cudaEventDisableTiming);
        cudaEventCreateWithFlags(&join, cudaEventDisableTiming);
    }
};
static SideStream g_side;

// ---------------------------------------------------------------------------
// Tiled SGEMM: C[M,N] = A[M,K] @ B[K,N]. BM=128, BN=64, BK=16, 256 thr,
// 8x4 per thread. H > 0: fused GAT attention-logit epilogue (64-col block
// == one head; a_src/a_dst flattened index equals global output column).
// ---------------------------------------------------------------------------
template <int H>
__global__ void sgemm_kernel(const float* __restrict__ A, const float* __restrict__ B,
                             float* __restrict__ C, int M, int N, int K,
                             const float* __restrict__ a_src,
                             const float* __restrict__ a_dst) {
    __shared__ float As[16][132];  // transposed; 132*4=528 bytes (16B-mult stride)
    __shared__ float Bs[16][68];   // 68*4=272 bytes (16B-mult stride)
    const int bm = blockIdx.y * 128;
    const int bn = blockIdx.x * 64;
    const int tid = threadIdx.x;
    const int tx = tid & 15, ty = tid >> 4;   // 16 x 16 thread grid
    float acc[8][4] = {};
    for (int k0 = 0; k0 < K; k0 += 16) {
        // A tile: 128 rows x 16 k, 2 float4 loads / thread, scalar transposed stores
        {
            int r = tid >> 1, c8 = (tid & 1) * 8;
            int row = bm + r;
            float4 v0 = make_float4(0.f, 0.f, 0.f, 0.f);
            float4 v1 = make_float4(0.f, 0.f, 0.f, 0.f);
            if (row < M) {
                v0 = *(const float4*)&A[(size_t)row * K + k0 + c8];
                v1 = *(const float4*)&A[(size_t)row * K + k0 + c8 + 4];
            }
            As[c8 + 0][r] = v0.x; As[c8 + 1][r] = v0.y;
            As[c8 + 2][r] = v0.z; As[c8 + 3][r] = v0.w;
            As[c8 + 4][r] = v1.x; As[c8 + 5][r] = v1.y;
            As[c8 + 6][r] = v1.z; As[c8 + 7][r] = v1.w;
        }
        // B tile: 16 k x 64 cols, float4 loads + float4 smem stores
        {
            int r = tid >> 4, c4 = (tid & 15) * 4;
            float4 v = *(const float4*)&B[(size_t)(k0 + r) * N + bn + c4];
            *(float4*)&Bs[r][c4] = v;
        }
        __syncthreads();
        #pragma unroll
        for (int k = 0; k < 16; k++) {
            float4 a0 = *(const float4*)&As[k][ty * 8];
            float4 a1 = *(const float4*)&As[k][ty * 8 + 4];
            float4 b0 = *(const float4*)&Bs[k][tx * 4];
            float a[8] = {a0.x, a0.y, a0.z, a0.w, a1.x, a1.y, a1.z, a1.w};
            float b[4] = {b0.x, b0.y, b0.z, b0.w};
            #pragma unroll
            for (int i = 0; i < 8; i++)
                #pragma unroll
                for (int j = 0; j < 4; j++)
                    acc[i][j] = fmaf(a[i], b[j], acc[i][j]);
        }
        __syncthreads();
    }
    #pragma unroll
    for (int i = 0; i < 8; i++) {
        int row = bm + ty * 8 + i;
        if (row < M) {
            float4 o;
            o.x = acc[i][0]; o.y = acc[i][1]; o.z = acc[i][2]; o.w = acc[i][3];
            *(float4*)&C[(size_t)row * N + bn + tx * 4] = o;
        }
    }
    if (H > 0) {
        // attention logits: per-row dot of this head's 64 cols with a_src/a_dst
        const int hd = bn >> 6;
        float asr[4], adr[4];
        #pragma unroll
        for (int j = 0; j < 4; j++) {
            asr[j] = a_src[bn + tx * 4 + j];
            adr[j] = a_dst[bn + tx * 4 + j];
        }
        #pragma unroll
        for (int i = 0; i < 8; i++) {
            float s = 0.f, d = 0.f;
            #pragma unroll
            for (int j = 0; j < 4; j++) {
                s = fmaf(acc[i][j], asr[j], s);
                d = fmaf(acc[i][j], adr[j], d);
            }
            // reduce across the 16 tx lanes (xor offsets < 16 stay in-group)
            #pragma unroll
            for (int off = 8; off >= 1; off >>= 1) {
                s += __shfl_xor_sync(0xffffffffu, s, off);
                d += __shfl_xor_sync(0xffffffffu, d, off);
            }
            int row = bm + ty * 8 + i;
            if (tx == 0 && row < M) {
                g_als[row * H + hd] = s;
                g_ald[row * H + hd] = d;
            }
        }
    }
}

// ---------------------------------------------------------------------------
// CSR build (dst-indexed, real edges only; self-loops handled inline later)
// 4 edges per thread for atomic ILP.
// ---------------------------------------------------------------------------
__global__ void degi_kernel(const int* __restrict__ dst, int E) {
    int t = blockIdx.x * blockDim.x + threadIdx.x;
    int e0 = t * 4;
    if (e0 + 3 < E) {
        int d0 = dst[e0], d1 = dst[e0 + 1], d2 = dst[e0 + 2], d3 = dst[e0 + 3];
        atomicAdd(&g_degi[d0], 1);
        atomicAdd(&g_degi[d1], 1);
        atomicAdd(&g_degi[d2], 1);
        atomicAdd(&g_degi[d3], 1);
    } else {
        for (int e = e0; e < E; e++) atomicAdd(&g_degi[dst[e]], 1);
    }
}

__global__ void scan_reduce_kernel(int n) {
    __shared__ int red[512];
    const int b = blockIdx.x, t = threadIdx.x;
    const int base = b * SCAN_CHUNK;
    int s = 0;
    #pragma unroll
    for (int i = t; i < SCAN_CHUNK; i += 512) {
        int idx = base + i;
        if (idx < n) s += g_degi[idx];
    }
    red[t] = s;
    __syncthreads();
    #pragma unroll
    for (int off = 256; off > 0; off >>= 1) {
        if (t < off) red[t] += red[t + off];
        __syncthreads();
    }
    if (t == 0) g_bsum[b] = red[0];
}

// per-block scan via warp shuffles (2 barriers); block offset inline (nb<=13)
__global__ void scan_write_kernel(int n) {
    __shared__ int wsum[16];
    const int b = blockIdx.x, t = threadIdx.x;
    const int lane = t & 31, wid = t >> 5;
    const int start = b * SCAN_CHUNK + t * 8;
    int vals[8];
    int s = 0;
    #pragma unroll
    for (int i = 0; i < 8; i++) {
        int idx = start + i;
        vals[i] = (idx < n) ? g_degi[idx] : 0;
        s += vals[i];
    }
    // warp inclusive scan of per-thread sums
    int ps = s;
    #pragma unroll
    for (int off = 1; off < 32; off <<= 1) {
        int v = __shfl_up_sync(0xffffffffu, ps, off);
        if (lane >= off) ps += v;
    }
    if (lane == 31) wsum[wid] = ps;
    __syncthreads();
    if (wid == 0 && lane < 16) {
        int v = wsum[lane];
        #pragma unroll
        for (int off = 1; off < 16; off <<= 1) {
            int u = __shfl_up_sync(0x0000ffffu, v, off);
            if (lane >= off) v += u;
        }
        wsum[lane] = v;   // inclusive warp-sums
    }
    __syncthreads();
    int boff = 0;
    for (int i = 0; i < b; i++) boff += g_bsum[i];
    int excl = boff + ((wid > 0) ? wsum[wid - 1] : 0) + (ps - s);
    #pragma unroll
    for (int i = 0; i < 8; i++) {
        int idx = start + i;
        if (idx < n) {
            g_rowptr[idx] = excl;
            g_cursor[idx] = excl;
            g_dis[idx] = rsqrtf((float)(vals[i] + 1));  // +1 self-loop
            excl += vals[i];
            if (idx == n - 1) g_rowptr[n] = excl;
        }
    }
}

__global__ void csr_fill_kernel(const int* __restrict__ src,
                                const int* __restrict__ dst, int E) {
    int t = blockIdx.x * blockDim.x + threadIdx.x;
    int e0 = t * 4;
    if (e0 + 3 < E) {
        int d0 = dst[e0], d1 = dst[e0 + 1], d2 = dst[e0 + 2], d3 = dst[e0 + 3];
        int s0 = src[e0], s1 = src[e0 + 1], s2 = src[e0 + 2], s3 = src[e0 + 3];
        int p0 = atomicAdd(&g_cursor[d0], 1);
        int p1 = atomicAdd(&g_cursor[d1], 1);
        int p2 = atomicAdd(&g_cursor[d2], 1);
        int p3 = atomicAdd(&g_cursor[d3], 1);
        g_col[p0] = s0; g_col[p1] = s1; g_col[p2] = s2; g_col[p3] = s3;
    } else {
        for (int e = e0; e < E; e++) {
            int pos = atomicAdd(&g_cursor[dst[e]], 1);
            g_col[pos] = src[e];
        }
    }
}

// ---------------------------------------------------------------------------
// GCN aggregation: warp per node, register-staged edges (shfl broadcast),
// next-chunk prefetch, 4-unrolled inner loop. Bias + relu fused.
// ---------------------------------------------------------------------------
__global__ void gcn_gather_kernel(const float* __restrict__ b1, int n) {
    const int w = (blockIdx.x * blockDim.x + threadIdx.x) >> 5;
    const int lane = threadIdx.x & 31;
    if (w >= n) return;
    const int d = w;
    const float dd = g_dis[d];
    const float2 sv = *(const float2*)&g_bufA[(size_t)d * 64 + lane * 2];
    float ax = dd * dd * sv.x;
    float ay = dd * dd * sv.y;
    const int beg = g_rowptr[d], end = g_rowptr[d + 1];

    int curC = 0; float curW = 0.f;
    {
        int j = beg + lane;
        if (j < end) { curC = g_col[j]; curW = g_dis[curC] * dd; }
    }
    for (int j0 = beg; j0 < end; j0 += 32) {
        const int cnt = min(32, end - j0);
        int pC = curC; float pW = curW;
        // prefetch next chunk (issues LDGs before the consume loop)
        int jn = j0 + 32 + lane;
        if (jn < end) { curC = g_col[jn]; curW = g_dis[curC] * dd; }

        auto proc = [&](int k) {
            int s = __shfl_sync(0xffffffffu, pC, k);
            float ws = __shfl_sync(0xffffffffu, pW, k);
            const float2 v = *(const float2*)&g_bufA[(size_t)s * 64 + lane * 2];
            ax = fmaf(ws, v.x, ax);
            ay = fmaf(ws, v.y, ay);
        };
        int k = 0;
        for (; k + 4 <= cnt; k += 4) { proc(k); proc(k + 1); proc(k + 2); proc(k + 3); }
        for (; k < cnt; k++) proc(k);
    }
    ax += b1[lane * 2];
    ay += b1[lane * 2 + 1];
    float2 o;
    o.x = ax > 0.0f ? ax : 0.0f;
    o.y = ay > 0.0f ? ay : 0.0f;
    *(float2*)&g_bufB[(size_t)d * 64 + lane * 2] = o;
}

// ---------------------------------------------------------------------------
// GAT aggregation: warp per node, register-staged edges + prefetch,
// chunk-max online softmax, owner-lane exp (1 MUFU / edge·head / warp).
// ---------------------------------------------------------------------------
template <int H, int F, bool RELU>
__global__ void gat_gather_kernel(const float* __restrict__ bias, int n,
                                  float* __restrict__ out) {
    constexpr int HF = H * F;
    constexpr int VPL = HF / 32;          // values per lane (2 or 4)
    const int w = (blockIdx.x * blockDim.x + threadIdx.x) >> 5;
    const int lane = threadIdx.x & 31;
    if (w >= n) return;
    const int d = w;
    const int hd = (lane * VPL) / F;      // this lane's head

    float ald_d[H], m[H], l[H];
    #pragma unroll
    for (int h = 0; h < H; h++) {
        ald_d[h] = g_ald[d * H + h];
        float v = g_als[d * H + h] + ald_d[h];
        v = v > 0.0f ? v : 0.2f * v;      // leaky relu
        m[h] = v;
        l[h] = 1.0f;
    }

    // self-loop contribution (exp(v - m) = 1 at init)
    float acc[VPL];
    {
        const float* sp = &g_bufA[(size_t)d * HF + lane * VPL];
        if (VPL == 4) {
            const float4 v = *(const float4*)sp;
            acc[0] = v.x; acc[1] = v.y; acc[2] = v.z; acc[3] = v.w;
        } else {
            const float2 v = *(const float2*)sp;
            acc[0] = v.x; acc[1] = v.y;
        }
    }

    const int beg = g_rowptr[d], end = g_rowptr[d + 1];

    // stage one edge per lane: column + leaky-relu'd logits
    auto stage = [&](int j0, int& c, float (&v)[H]) {
        c = 0;
        #pragma unroll
        for (int h = 0; h < H; h++) v[h] = -3.0e38f;
        int j = j0 + lane;
        if (j < end) {
            c = g_col[j];
            #pragma unroll
            for (int h = 0; h < H; h++) {
                float t = g_als[c * H + h] + ald_d[h];
                v[h] = t > 0.0f ? t : 0.2f * t;
            }
        }
    };

    int curC; float curV[H];
    stage(beg, curC, curV);
    for (int j0 = beg; j0 < end; j0 += 32) {
        const int cnt = min(32, end - j0);
        int pC = curC;
        float pV[H];
        #pragma unroll
        for (int h = 0; h < H; h++) pV[h] = curV[h];
        stage(j0 + 32, curC, curV);   // prefetch next chunk

        // chunk max per head + single rescale
        #pragma unroll
        for (int h = 0; h < H; h++) {
            float cm = pV[h];
            #pragma unroll
            for (int off = 16; off >= 1; off >>= 1)
                cm = fmaxf(cm, __shfl_xor_sync(0xffffffffu, cm, off));
            if (cm > m[h]) {
                float r = __expf(m[h] - cm);
                l[h] *= r;
                if (h == ((H == 2) ? hd : 0)) {
                    #pragma unroll
                    for (int i = 0; i < VPL; i++) acc[i] *= r;
                }
                m[h] = cm;
            }
        }
        // owner-lane exponentials (once per edge-head, broadcast in proc)
        float pE[H];
        #pragma unroll
        for (int h = 0; h < H; h++) pE[h] = __expf(pV[h] - m[h]);

        auto proc = [&](int k) {
            int s = __shfl_sync(0xffffffffu, pC, k);
            float e0 = __shfl_sync(0xffffffffu, pE[0], k);
            l[0] += e0;
            float ee = e0;
            if (H == 2) {
                float e1 = __shfl_sync(0xffffffffu, pE[1], k);
                l[1] += e1;
                if (hd == 1) ee = e1;
            }
            const float* sp = &g_bufA[(size_t)s * HF + lane * VPL];
            if (VPL == 4) {
                const float4 v = *(const float4*)sp;
                acc[0] = fmaf(ee, v.x, acc[0]);
                acc[1] = fmaf(ee, v.y, acc[1]);
                acc[2] = fmaf(ee, v.z, acc[2]);
                acc[3] = fmaf(ee, v.w, acc[3]);
            } else {
                const float2 v = *(const float2*)sp;
                acc[0] = fmaf(ee, v.x, acc[0]);
                acc[1] = fmaf(ee, v.y, acc[1]);
            }
        };
        int k = 0;
        for (; k + 4 <= cnt; k += 4) { proc(k); proc(k + 1); proc(k + 2); proc(k + 3); }
        for (; k < cnt; k++) proc(k);
    }

    const float inv = 1.0f / ((H == 2 && hd == 1) ? l[1] : l[0]);
    #pragma unroll
    for (int i = 0; i < VPL; i++) {
        float v = acc[i] * inv + bias[lane * VPL + i];
        if (RELU) v = v > 0.0f ? v : 0.0f;
        acc[i] = v;
    }
    float* op = &out[(size_t)d * HF + lane * VPL];
    if (VPL == 4) {
        float4 o; o.x = acc[0]; o.y = acc[1]; o.z = acc[2]; o.w = acc[3];
        *(float4*)op = o;
    } else {
        float2 o; o.x = acc[0]; o.y = acc[1];
        *(float2*)op = o;
    }
}

// ---------------------------------------------------------------------------
// Pooling + classifier
// ---------------------------------------------------------------------------
__global__ void pool_kernel(const int* __restrict__ batch, int n) {
    int t = blockIdx.x * blockDim.x + threadIdx.x;
    int node = t >> 4, lane = t & 15;
    if (node >= n) return;
    int g = batch[node];
    const float4 v = *(const float4*)&g_bufB[(size_t)node * 64 + lane * 4];
    float* o = &g_sums[g * 64 + lane * 4];
    atomicAdd(o + 0, v.x);
    atomicAdd(o + 1, v.y);
    atomicAdd(o + 2, v.z);
    atomicAdd(o + 3, v.w);
    if (lane == 0) atomicAdd(&g_cnt[g], 1.0f);
}

__global__ void final_kernel(const float* __restrict__ Wfc, const float* __restrict__ bfc,
                             float* __restrict__ out, int G) {
    int g = blockIdx.x * blockDim.x + threadIdx.x;
    if (g >= G) return;
    float c = fmaxf(g_cnt[g], 1.0f);
    float l0 = bfc[0], l1 = bfc[1];
    #pragma unroll
    for (int f = 0; f < 64; f++) {
        float p = g_sums[g * 64 + f] / c;
        l0 = fmaf(p, Wfc[f * 2 + 0], l0);
        l1 = fmaf(p, Wfc[f * 2 + 1], l1);
    }
    float m = fmaxf(l0, l1);
    float lse = m + logf(expf(l0 - m) + expf(l1 - m));
    out[2 * g + 0] = l0 - lse;
    out[2 * g + 1] = l1 - lse;
}

// ---------------------------------------------------------------------------
// Host launcher
// ---------------------------------------------------------------------------
extern "C" void kernel_launch(void* const* d_in, const int* in_sizes, int n_in,
                              void* d_out, int out_size) {
    const float* x    = (const float*)d_in[0];
    const int*   ei   = (const int*)d_in[1];
    const int*   bat  = (const int*)d_in[2];
    const float* W1   = (const float*)d_in[3];
    const float* b1   = (const float*)d_in[4];
    const float* W2   = (const float*)d_in[5];
    const float* as2  = (const float*)d_in[6];
    const float* ad2  = (const float*)d_in[7];
    const float* b2   = (const float*)d_in[8];
    const float* W3   = (const float*)d_in[9];
    const float* as3  = (const float*)d_in[10];
    const float* ad3  = (const float*)d_in[11];
    const float* b3   = (const float*)d_in[12];
    const float* Wfc  = (const float*)d_in[13];
    const float* bfc  = (const float*)d_in[14];

    const int n  = in_sizes[0] / 128;   // 50000
    const int E  = in_sizes[1] / 2;     // 800000
    const int G  = out_size / 2;        // 512
    const int* src = ei;
    const int* dst = ei + E;
    const int nb = (n + SCAN_CHUNK - 1) / SCAN_CHUNK;

    void *pBufA, *pBufB, *pDegi, *pSums, *pCnt;
    cudaGetSymbolAddress(&pBufA, g_bufA);
    cudaGetSymbolAddress(&pBufB, g_bufB);
    cudaGetSymbolAddress(&pDegi, g_degi);
    cudaGetSymbolAddress(&pSums, g_sums);
    cudaGetSymbolAddress(&pCnt,  g_cnt);

    const int TB = 256;
    auto cdiv = [](long long a, long long b) { return (int)((a + b - 1) / b); };
    cudaStream_t s2 = g_side.s;
    const int E4 = cdiv(E, 4);   // edge-quads for the 4x ILP kernels

    // ===== Fork: CSR build on side stream, GEMM1 on main stream =====
    cudaEventRecord(g_side.fork, 0);
    cudaStreamWaitEvent(s2, g_side.fork, 0);

    cudaMemsetAsync(pDegi, 0, (size_t)n * sizeof(int), s2);
    cudaMemsetAsync(pSums, 0, (size_t)G * 64 * sizeof(float), s2);
    cudaMemsetAsync(pCnt,  0, (size_t)G * sizeof(float), s2);
    degi_kernel<<<cdiv(E4, TB), TB, 0, s2>>>(dst, E);
    scan_reduce_kernel<<<nb, 512, 0, s2>>>(n);
    scan_write_kernel<<<nb, 512, 0, s2>>>(n);
    csr_fill_kernel<<<cdiv(E4, TB), TB, 0, s2>>>(src, dst, E);
    cudaEventRecord(g_side.join, s2);

    sgemm_kernel<0><<<dim3(1, cdiv(n, 128)), TB>>>(x, W1, (float*)pBufA, n, 64, 128, nullptr, nullptr);

    // ===== Join, then layer 1: GCNConv(128 -> 64) + relu (fused) =====
    cudaStreamWaitEvent(0, g_side.join, 0);
    gcn_gather_kernel<<<cdiv((long long)n * 32, TB), TB>>>(b1, n);

    // ===== Layer 2: GATConv(64 -> 64, heads=2, concat) + relu =====
    sgemm_kernel<2><<<dim3(2, cdiv(n, 128)), TB>>>((const float*)pBufB, W2, (float*)pBufA, n, 128, 64, as2, ad2);
    gat_gather_kernel<2, 64, true><<<cdiv((long long)n * 32, TB), TB>>>(b2, n, (float*)pBufB);

    // ===== Layer 3: GATConv(128 -> 64, heads=1, mean) =====
    sgemm_kernel<1><<<dim3(1, cdiv(n, 128)), TB>>>((const float*)pBufB, W3, (float*)pBufA, n, 64, 128, as3, ad3);
    gat_gather_kernel<1, 64, false><<<cdiv((long long)n * 32, TB), TB>>>(b3, n, (float*)pBufB);

    // ===== Mean pool + FC + log_softmax =====
    pool_kernel<<<cdiv((long long)n * 16, TB), TB>>>(bat, n);
    final_kernel<<<cdiv(G, TB), TB>>>(Wfc, bfc, (float*)d_out, G);
}

// round 13
// speedup vs baseline: 1.1415x; 1.1415x over previous
#include <cuda_runtime.h>
#include <cstdint>

// ---------------------------------------------------------------------------
// Problem constants (shapes fixed by the dataset)
// ---------------------------------------------------------------------------
#define MAXN 50048            // >= N=50000
#define MAXE 800000
#define MAXG 512
#define SCAN_CHUNK 4096       // elements per scan block (512 thr * 8)
#define MAXSB ((MAXN + SCAN_CHUNK - 1) / SCAN_CHUNK)

// ---------------------------------------------------------------------------
// Device scratch (static allocation — no cudaMalloc allowed)
// ---------------------------------------------------------------------------
__device__ __align__(16) float g_bufA[(size_t)MAXN * 128]; // GEMM outputs (transformed feats)
__device__ __align__(16) float g_bufB[(size_t)MAXN * 128]; // layer outputs
__device__ int   g_degi[MAXN];
__device__ int   g_rowptr[MAXN + 1];
__device__ int   g_cursor[MAXN];
__device__ int   g_col[MAXE];
__device__ int   g_bsum[MAXSB];
__device__ float g_dis[MAXN];
__device__ __align__(8) float g_als[MAXN * 2];
__device__ __align__(8) float g_ald[MAXN * 2];
__device__ __align__(16) float g_sums[MAXG * 64];
__device__ float g_cnt[MAXG];

// ---------------------------------------------------------------------------
// Side stream + events for fork/join inside graph capture (created once at
// process init; kernel_launch itself performs identical work every call).
// ---------------------------------------------------------------------------
struct SideStream {
    cudaStream_t s;
    cudaEvent_t fork, join;
    SideStream() {
        cudaStreamCreateWithFlags(&s, cudaStreamNonBlocking);
        cudaEventCreateWithFlags(&fork, cudaEventDisableTiming);
        cudaEventCreateWithFlags(&join, cudaEventDisableTiming);
    }
};
static SideStream g_side;

// ---------------------------------------------------------------------------
// Tiled SGEMM: C[M,N] = A[M,K] @ B[K,N]. BM=128, BN=64, BK=16, 256 thr,
// 8x4 per thread. H > 0: fused GAT attention-logit epilogue (64-col block
// == one head; a_src/a_dst flattened index equals global output column).
// ---------------------------------------------------------------------------
template <int H>
__global__ void sgemm_kernel(const float* __restrict__ A, const float* __restrict__ B,
                             float* __restrict__ C, int M, int N, int K,
                             const float* __restrict__ a_src,
                             const float* __restrict__ a_dst) {
    __shared__ float As[16][132];  // transposed; 132*4=528 bytes (16B-mult stride)
    __shared__ float Bs[16][68];   // 68*4=272 bytes (16B-mult stride)
    const int bm = blockIdx.y * 128;
    const int bn = blockIdx.x * 64;
    const int tid = threadIdx.x;
    const int tx = tid & 15, ty = tid >> 4;   // 16 x 16 thread grid
    float acc[8][4] = {};
    for (int k0 = 0; k0 < K; k0 += 16) {
        // A tile: 128 rows x 16 k, 2 float4 loads / thread, scalar transposed stores
        {
            int r = tid >> 1, c8 = (tid & 1) * 8;
            int row = bm + r;
            float4 v0 = make_float4(0.f, 0.f, 0.f, 0.f);
            float4 v1 = make_float4(0.f, 0.f, 0.f, 0.f);
            if (row < M) {
                v0 = *(const float4*)&A[(size_t)row * K + k0 + c8];
                v1 = *(const float4*)&A[(size_t)row * K + k0 + c8 + 4];
            }
            As[c8 + 0][r] = v0.x; As[c8 + 1][r] = v0.y;
            As[c8 + 2][r] = v0.z; As[c8 + 3][r] = v0.w;
            As[c8 + 4][r] = v1.x; As[c8 + 5][r] = v1.y;
            As[c8 + 6][r] = v1.z; As[c8 + 7][r] = v1.w;
        }
        // B tile: 16 k x 64 cols, float4 loads + float4 smem stores
        {
            int r = tid >> 4, c4 = (tid & 15) * 4;
            float4 v = *(const float4*)&B[(size_t)(k0 + r) * N + bn + c4];
            *(float4*)&Bs[r][c4] = v;
        }
        __syncthreads();
        #pragma unroll
        for (int k = 0; k < 16; k++) {
            float4 a0 = *(const float4*)&As[k][ty * 8];
            float4 a1 = *(const float4*)&As[k][ty * 8 + 4];
            float4 b0 = *(const float4*)&Bs[k][tx * 4];
            float a[8] = {a0.x, a0.y, a0.z, a0.w, a1.x, a1.y, a1.z, a1.w};
            float b[4] = {b0.x, b0.y, b0.z, b0.w};
            #pragma unroll
            for (int i = 0; i < 8; i++)
                #pragma unroll
                for (int j = 0; j < 4; j++)
                    acc[i][j] = fmaf(a[i], b[j], acc[i][j]);
        }
        __syncthreads();
    }
    #pragma unroll
    for (int i = 0; i < 8; i++) {
        int row = bm + ty * 8 + i;
        if (row < M) {
            float4 o;
            o.x = acc[i][0]; o.y = acc[i][1]; o.z = acc[i][2]; o.w = acc[i][3];
            *(float4*)&C[(size_t)row * N + bn + tx * 4] = o;
        }
    }
    if (H > 0) {
        // attention logits: per-row dot of this head's 64 cols with a_src/a_dst
        const int hd = bn >> 6;
        float asr[4], adr[4];
        #pragma unroll
        for (int j = 0; j < 4; j++) {
            asr[j] = a_src[bn + tx * 4 + j];
            adr[j] = a_dst[bn + tx * 4 + j];
        }
        #pragma unroll
        for (int i = 0; i < 8; i++) {
            float s = 0.f, d = 0.f;
            #pragma unroll
            for (int j = 0; j < 4; j++) {
                s = fmaf(acc[i][j], asr[j], s);
                d = fmaf(acc[i][j], adr[j], d);
            }
            // reduce across the 16 tx lanes (xor offsets < 16 stay in-group)
            #pragma unroll
            for (int off = 8; off >= 1; off >>= 1) {
                s += __shfl_xor_sync(0xffffffffu, s, off);
                d += __shfl_xor_sync(0xffffffffu, d, off);
            }
            int row = bm + ty * 8 + i;
            if (tx == 0 && row < M) {
                g_als[row * H + hd] = s;
                g_ald[row * H + hd] = d;
            }
        }
    }
}

// ---------------------------------------------------------------------------
// CSR build (dst-indexed, real edges only; self-loops handled inline later)
// ---------------------------------------------------------------------------
__global__ void degi_kernel(const int* __restrict__ dst, int E) {
    int i = blockIdx.x * blockDim.x + threadIdx.x;
    if (i < E) atomicAdd(&g_degi[dst[i]], 1);
}

__global__ void scan_reduce_kernel(int n) {
    __shared__ int red[512];
    const int b = blockIdx.x, t = threadIdx.x;
    const int base = b * SCAN_CHUNK;
    int s = 0;
    #pragma unroll
    for (int i = t; i < SCAN_CHUNK; i += 512) {
        int idx = base + i;
        if (idx < n) s += g_degi[idx];
    }
    red[t] = s;
    __syncthreads();
    #pragma unroll
    for (int off = 256; off > 0; off >>= 1) {
        if (t < off) red[t] += red[t + off];
        __syncthreads();
    }
    if (t == 0) g_bsum[b] = red[0];
}

// per-block scan via warp shuffles (2 barriers); block offset inline (nb<=13)
__global__ void scan_write_kernel(int n) {
    __shared__ int wsum[16];
    const int b = blockIdx.x, t = threadIdx.x;
    const int lane = t & 31, wid = t >> 5;
    const int start = b * SCAN_CHUNK + t * 8;
    int vals[8];
    int s = 0;
    #pragma unroll
    for (int i = 0; i < 8; i++) {
        int idx = start + i;
        vals[i] = (idx < n) ? g_degi[idx] : 0;
        s += vals[i];
    }
    // warp inclusive scan of per-thread sums
    int ps = s;
    #pragma unroll
    for (int off = 1; off < 32; off <<= 1) {
        int v = __shfl_up_sync(0xffffffffu, ps, off);
        if (lane >= off) ps += v;
    }
    if (lane == 31) wsum[wid] = ps;
    __syncthreads();
    if (wid == 0 && lane < 16) {
        int v = wsum[lane];
        #pragma unroll
        for (int off = 1; off < 16; off <<= 1) {
            int u = __shfl_up_sync(0x0000ffffu, v, off);
            if (lane >= off) v += u;
        }
        wsum[lane] = v;   // inclusive warp-sums
    }
    __syncthreads();
    int boff = 0;
    for (int i = 0; i < b; i++) boff += g_bsum[i];
    int excl = boff + ((wid > 0) ? wsum[wid - 1] : 0) + (ps - s);
    #pragma unroll
    for (int i = 0; i < 8; i++) {
        int idx = start + i;
        if (idx < n) {
            g_rowptr[idx] = excl;
            g_cursor[idx] = excl;
            g_dis[idx] = rsqrtf((float)(vals[i] + 1));  // +1 self-loop
            excl += vals[i];
            if (idx == n - 1) g_rowptr[n] = excl;
        }
    }
}

__global__ void csr_fill_kernel(const int* __restrict__ src,
                                const int* __restrict__ dst, int E) {
    int e = blockIdx.x * blockDim.x + threadIdx.x;
    if (e >= E) return;
    int pos = atomicAdd(&g_cursor[dst[e]], 1);
    g_col[pos] = src[e];
}

// ---------------------------------------------------------------------------
// GCN aggregation: warp per node, smem-staged edges, 4-unrolled inner loop.
// ---------------------------------------------------------------------------
__global__ void gcn_gather_kernel(const float* __restrict__ b1, int n) {
    __shared__ int   s_col[8][32];
    __shared__ float s_wt[8][32];
    const int w = (blockIdx.x * blockDim.x + threadIdx.x) >> 5;
    const int lane = threadIdx.x & 31;
    const int wrp = threadIdx.x >> 5;
    if (w >= n) return;
    const int d = w;
    const float dd = g_dis[d];
    const float2 sv = *(const float2*)&g_bufA[(size_t)d * 64 + lane * 2];
    float ax = dd * dd * sv.x;
    float ay = dd * dd * sv.y;
    const int beg = g_rowptr[d], end = g_rowptr[d + 1];

    auto proc = [&](int k) {
        int s = s_col[wrp][k];
        float ws = s_wt[wrp][k];
        const float2 v = *(const float2*)&g_bufA[(size_t)s * 64 + lane * 2];
        ax = fmaf(ws, v.x, ax);
        ay = fmaf(ws, v.y, ay);
    };

    for (int j0 = beg; j0 < end; j0 += 32) {
        const int cnt = min(32, end - j0);
        if (lane < cnt) {
            int s = g_col[j0 + lane];
            s_col[wrp][lane] = s;
            s_wt[wrp][lane] = g_dis[s] * dd;
        }
        __syncwarp();
        int k = 0;
        for (; k + 4 <= cnt; k += 4) { proc(k); proc(k + 1); proc(k + 2); proc(k + 3); }
        for (; k < cnt; k++) proc(k);
        __syncwarp();
    }
    ax += b1[lane * 2];
    ay += b1[lane * 2 + 1];
    float2 o;
    o.x = ax > 0.0f ? ax : 0.0f;
    o.y = ay > 0.0f ? ay : 0.0f;
    *(float2*)&g_bufB[(size_t)d * 64 + lane * 2] = o;
}

// ---------------------------------------------------------------------------
// GAT aggregation: warp per node, smem-staged edges, chunk-max online
// softmax. Exponentials are computed ONCE per edge (in-place on the staged
// logits) after the chunk-max update; the consume loop reads exps via LDS.
// ---------------------------------------------------------------------------
template <int H, int F, bool RELU>
__global__ void gat_gather_kernel(const float* __restrict__ bias, int n,
                                  float* __restrict__ out) {
    constexpr int HF = H * F;
    constexpr int VPL = HF / 32;          // values per lane (2 or 4)
    __shared__ int   s_col[8][32];
    __shared__ float s_e[8][H * 32];      // staged logits -> exps (in-place)
    const int w = (blockIdx.x * blockDim.x + threadIdx.x) >> 5;
    const int lane = threadIdx.x & 31;
    const int wrp = threadIdx.x >> 5;
    if (w >= n) return;
    const int d = w;
    const int hd = (lane * VPL) / F;      // this lane's head

    float ald_d[H], m[H], l[H];
    #pragma unroll
    for (int h = 0; h < H; h++) {
        ald_d[h] = g_ald[d * H + h];
        float v = g_als[d * H + h] + ald_d[h];
        v = v > 0.0f ? v : 0.2f * v;      // leaky relu
        m[h] = v;
        l[h] = 1.0f;
    }

    // self-loop contribution (exp(v - m) = 1 at init)
    float acc[VPL];
    {
        const float* sp = &g_bufA[(size_t)d * HF + lane * VPL];
        if (VPL == 4) {
            const float4 v = *(const float4*)sp;
            acc[0] = v.x; acc[1] = v.y; acc[2] = v.z; acc[3] = v.w;
        } else {
            const float2 v = *(const float2*)sp;
            acc[0] = v.x; acc[1] = v.y;
        }
    }

    const int beg = g_rowptr[d], end = g_rowptr[d + 1];

    auto proc = [&](int k) {
        int s = s_col[wrp][k];
        float ex0 = s_e[wrp][k];          // already exponentiated
        l[0] += ex0;
        float ee = ex0;
        if (H == 2) {
            float ex1 = s_e[wrp][32 + k];
            l[1] += ex1;
            if (hd == 1) ee = ex1;
        }
        const float* sp = &g_bufA[(size_t)s * HF + lane * VPL];
        if (VPL == 4) {
            const float4 v = *(const float4*)sp;
            acc[0] = fmaf(ee, v.x, acc[0]);
            acc[1] = fmaf(ee, v.y, acc[1]);
            acc[2] = fmaf(ee, v.z, acc[2]);
            acc[3] = fmaf(ee, v.w, acc[3]);
        } else {
            const float2 v = *(const float2*)sp;
            acc[0] = fmaf(ee, v.x, acc[0]);
            acc[1] = fmaf(ee, v.y, acc[1]);
        }
    };

    for (int j0 = beg; j0 < end; j0 += 32) {
        const int cnt = min(32, end - j0);
        float myv[H];
        #pragma unroll
        for (int h = 0; h < H; h++) myv[h] = -3.0e38f;
        if (lane < cnt) {
            int s = g_col[j0 + lane];
            s_col[wrp][lane] = s;
            #pragma unroll
            for (int h = 0; h < H; h++) {
                float v = g_als[s * H + h] + ald_d[h];
                v = v > 0.0f ? v : 0.2f * v;
                myv[h] = v;
            }
        }
        // chunk max per head + single rescale (m is warp-uniform afterwards)
        #pragma unroll
        for (int h = 0; h < H; h++) {
            float cm = myv[h];
            #pragma unroll
            for (int off = 16; off >= 1; off >>= 1)
                cm = fmaxf(cm, __shfl_xor_sync(0xffffffffu, cm, off));
            if (cm > m[h]) {
                float r = __expf(m[h] - cm);
                l[h] *= r;
                if (h == ((H == 2) ? hd : 0)) {
                    #pragma unroll
                    for (int i = 0; i < VPL; i++) acc[i] *= r;
                }
                m[h] = cm;
            }
        }
        // owner-lane exponentiation: one MUFU per edge-head for the warp
        if (lane < cnt) {
            #pragma unroll
            for (int h = 0; h < H; h++)
                s_e[wrp][h * 32 + lane] = __expf(myv[h] - m[h]);
        }
        __syncwarp();
        int k = 0;
        for (; k + 4 <= cnt; k += 4) { proc(k); proc(k + 1); proc(k + 2); proc(k + 3); }
        for (; k < cnt; k++) proc(k);
        __syncwarp();
    }

    const float inv = 1.0f / ((H == 2 && hd == 1) ? l[1] : l[0]);
    #pragma unroll
    for (int i = 0; i < VPL; i++) {
        float v = acc[i] * inv + bias[lane * VPL + i];
        if (RELU) v = v > 0.0f ? v : 0.0f;
        acc[i] = v;
    }
    float* op = &out[(size_t)d * HF + lane * VPL];
    if (VPL == 4) {
        float4 o; o.x = acc[0]; o.y = acc[1]; o.z = acc[2]; o.w = acc[3];
        *(float4*)op = o;
    } else {
        float2 o; o.x = acc[0]; o.y = acc[1];
        *(float2*)op = o;
    }
}

// ---------------------------------------------------------------------------
// Pooling + classifier
// ---------------------------------------------------------------------------
__global__ void pool_kernel(const int* __restrict__ batch, int n) {
    int t = blockIdx.x * blockDim.x + threadIdx.x;
    int node = t >> 4, lane = t & 15;
    if (node >= n) return;
    int g = batch[node];
    const float4 v = *(const float4*)&g_bufB[(size_t)node * 64 + lane * 4];
    float* o = &g_sums[g * 64 + lane * 4];
    atomicAdd(o + 0, v.x);
    atomicAdd(o + 1, v.y);
    atomicAdd(o + 2, v.z);
    atomicAdd(o + 3, v.w);
    if (lane == 0) atomicAdd(&g_cnt[g], 1.0f);
}

__global__ void final_kernel(const float* __restrict__ Wfc, const float* __restrict__ bfc,
                             float* __restrict__ out, int G) {
    int g = blockIdx.x * blockDim.x + threadIdx.x;
    if (g >= G) return;
    float c = fmaxf(g_cnt[g], 1.0f);
    float l0 = bfc[0], l1 = bfc[1];
    #pragma unroll
    for (int f = 0; f < 64; f++) {
        float p = g_sums[g * 64 + f] / c;
        l0 = fmaf(p, Wfc[f * 2 + 0], l0);
        l1 = fmaf(p, Wfc[f * 2 + 1], l1);
    }
    float m = fmaxf(l0, l1);
    float lse = m + logf(expf(l0 - m) + expf(l1 - m));
    out[2 * g + 0] = l0 - lse;
    out[2 * g + 1] = l1 - lse;
}

// ---------------------------------------------------------------------------
// Host launcher
// ---------------------------------------------------------------------------
extern "C" void kernel_launch(void* const* d_in, const int* in_sizes, int n_in,
                              void* d_out, int out_size) {
    const float* x    = (const float*)d_in[0];
    const int*   ei   = (const int*)d_in[1];
    const int*   bat  = (const int*)d_in[2];
    const float* W1   = (const float*)d_in[3];
    const float* b1   = (const float*)d_in[4];
    const float* W2   = (const float*)d_in[5];
    const float* as2  = (const float*)d_in[6];
    const float* ad2  = (const float*)d_in[7];
    const float* b2   = (const float*)d_in[8];
    const float* W3   = (const float*)d_in[9];
    const float* as3  = (const float*)d_in[10];
    const float* ad3  = (const float*)d_in[11];
    const float* b3   = (const float*)d_in[12];
    const float* Wfc  = (const float*)d_in[13];
    const float* bfc  = (const float*)d_in[14];

    const int n  = in_sizes[0] / 128;   // 50000
    const int E  = in_sizes[1] / 2;     // 800000
    const int G  = out_size / 2;        // 512
    const int* src = ei;
    const int* dst = ei + E;
    const int nb = (n + SCAN_CHUNK - 1) / SCAN_CHUNK;

    void *pBufA, *pBufB, *pDegi, *pSums, *pCnt;
    cudaGetSymbolAddress(&pBufA, g_bufA);
    cudaGetSymbolAddress(&pBufB, g_bufB);
    cudaGetSymbolAddress(&pDegi, g_degi);
    cudaGetSymbolAddress(&pSums, g_sums);
    cudaGetSymbolAddress(&pCnt,  g_cnt);

    const int TB = 256;
    auto cdiv = [](long long a, long long b) { return (int)((a + b - 1) / b); };
    cudaStream_t s2 = g_side.s;

    // ===== Fork: CSR build on side stream, GEMM1 on main stream =====
    cudaEventRecord(g_side.fork, 0);
    cudaStreamWaitEvent(s2, g_side.fork, 0);

    cudaMemsetAsync(pDegi, 0, (size_t)n * sizeof(int), s2);
    cudaMemsetAsync(pSums, 0, (size_t)G * 64 * sizeof(float), s2);
    cudaMemsetAsync(pCnt,  0, (size_t)G * sizeof(float), s2);
    degi_kernel<<<cdiv(E, TB), TB, 0, s2>>>(dst, E);
    scan_reduce_kernel<<<nb, 512, 0, s2>>>(n);
    scan_write_kernel<<<nb, 512, 0, s2>>>(n);
    csr_fill_kernel<<<cdiv(E, TB), TB, 0, s2>>>(src, dst, E);
    cudaEventRecord(g_side.join, s2);

    sgemm_kernel<0><<<dim3(1, cdiv(n, 128)), TB>>>(x, W1, (float*)pBufA, n, 64, 128, nullptr, nullptr);

    // ===== Join, then layer 1: GCNConv(128 -> 64) + relu (fused) =====
    cudaStreamWaitEvent(0, g_side.join, 0);
    gcn_gather_kernel<<<cdiv((long long)n * 32, TB), TB>>>(b1, n);

    // ===== Layer 2: GATConv(64 -> 64, heads=2, concat) + relu =====
    sgemm_kernel<2><<<dim3(2, cdiv(n, 128)), TB>>>((const float*)pBufB, W2, (float*)pBufA, n, 128, 64, as2, ad2);
    gat_gather_kernel<2, 64, true><<<cdiv((long long)n * 32, TB), TB>>>(b2, n, (float*)pBufB);

    // ===== Layer 3: GATConv(128 -> 64, heads=1, mean) =====
    sgemm_kernel<1><<<dim3(1, cdiv(n, 128)), TB>>>((const float*)pBufB, W3, (float*)pBufA, n, 64, 128, as3, ad3);
    gat_gather_kernel<1, 64, false><<<cdiv((long long)n * 32, TB), TB>>>(b3, n, (float*)pBufB);

    // ===== Mean pool + FC + log_softmax =====
    pool_kernel<<<cdiv((long long)n * 16, TB), TB>>>(bat, n);
    final_kernel<<<cdiv(G, TB), TB>>>(Wfc, bfc, (float*)d_out, G);
}

// round 15
// speedup vs baseline: 1.2438x; 1.0897x over previous
#include <cuda_runtime.h>
#include <cuda_fp16.h>
#include <cstdint>

// ---------------------------------------------------------------------------
// Problem constants (shapes fixed by the dataset)
// ---------------------------------------------------------------------------
#define MAXN 50048            // >= N=50000
#define MAXE 800000
#define MAXG 512
#define SCAN_CHUNK 4096       // elements per scan block (512 thr * 8)
#define MAXSB ((MAXN + SCAN_CHUNK - 1) / SCAN_CHUNK)

// ---------------------------------------------------------------------------
// Device scratch (static allocation — no cudaMalloc allowed)
// ---------------------------------------------------------------------------
__device__ __align__(16) __half g_bufA[(size_t)MAXN * 128]; // GEMM outputs (fp16 features)
__device__ __align__(16) float  g_bufB[(size_t)MAXN * 128]; // layer outputs (fp32)
__device__ int   g_degi[MAXN];
__device__ int   g_rowptr[MAXN + 1];
__device__ int   g_cursor[MAXN];
__device__ int   g_col[MAXE];
__device__ int   g_bsum[MAXSB];
__device__ float g_dis[MAXN];
__device__ __align__(8) float g_als[MAXN * 2];
__device__ __align__(8) float g_ald[MAXN * 2];
__device__ __align__(16) float g_sums[MAXG * 64];
__device__ float g_cnt[MAXG];

// ---------------------------------------------------------------------------
// Side stream + events for fork/join inside graph capture (created once at
// process init; kernel_launch itself performs identical work every call).
// ---------------------------------------------------------------------------
struct SideStream {
    cudaStream_t s;
    cudaEvent_t fork, join;
    SideStream() {
        cudaStreamCreateWithFlags(&s, cudaStreamNonBlocking);
        cudaEventCreateWithFlags(&fork, cudaEventDisableTiming);
        cudaEventCreateWithFlags(&join, cudaEventDisableTiming);
    }
};
static SideStream g_side;

// ---------------------------------------------------------------------------
// Tiled SGEMM: C[M,N] = A[M,K] @ B[K,N], fp32 compute, fp16 C output.
// BM=128, BN=64, BK=16, 256 thr, 8x4 per thread. H > 0: fused GAT
// attention-logit epilogue computed from fp32 accumulators.
// ---------------------------------------------------------------------------
template <int H>
__global__ void sgemm_kernel(const float* __restrict__ A, const float* __restrict__ B,
                             __half* __restrict__ C, int M, int N, int K,
                             const float* __restrict__ a_src,
                             const float* __restrict__ a_dst) {
    __shared__ float As[16][132];  // transposed; 528-byte stride (16B mult)
    __shared__ float Bs[16][68];   // 272-byte stride (16B mult)
    const int bm = blockIdx.y * 128;
    const int bn = blockIdx.x * 64;
    const int tid = threadIdx.x;
    const int tx = tid & 15, ty = tid >> 4;   // 16 x 16 thread grid
    float acc[8][4] = {};
    for (int k0 = 0; k0 < K; k0 += 16) {
        {
            int r = tid >> 1, c8 = (tid & 1) * 8;
            int row = bm + r;
            float4 v0 = make_float4(0.f, 0.f, 0.f, 0.f);
            float4 v1 = make_float4(0.f, 0.f, 0.f, 0.f);
            if (row < M) {
                v0 = *(const float4*)&A[(size_t)row * K + k0 + c8];
                v1 = *(const float4*)&A[(size_t)row * K + k0 + c8 + 4];
            }
            As[c8 + 0][r] = v0.x; As[c8 + 1][r] = v0.y;
            As[c8 + 2][r] = v0.z; As[c8 + 3][r] = v0.w;
            As[c8 + 4][r] = v1.x; As[c8 + 5][r] = v1.y;
            As[c8 + 6][r] = v1.z; As[c8 + 7][r] = v1.w;
        }
        {
            int r = tid >> 4, c4 = (tid & 15) * 4;
            float4 v = *(const float4*)&B[(size_t)(k0 + r) * N + bn + c4];
            *(float4*)&Bs[r][c4] = v;
        }
        __syncthreads();
        #pragma unroll
        for (int k = 0; k < 16; k++) {
            float4 a0 = *(const float4*)&As[k][ty * 8];
            float4 a1 = *(const float4*)&As[k][ty * 8 + 4];
            float4 b0 = *(const float4*)&Bs[k][tx * 4];
            float a[8] = {a0.x, a0.y, a0.z, a0.w, a1.x, a1.y, a1.z, a1.w};
            float b[4] = {b0.x, b0.y, b0.z, b0.w};
            #pragma unroll
            for (int i = 0; i < 8; i++)
                #pragma unroll
                for (int j = 0; j < 4; j++)
                    acc[i][j] = fmaf(a[i], b[j], acc[i][j]);
        }
        __syncthreads();
    }
    #pragma unroll
    for (int i = 0; i < 8; i++) {
        int row = bm + ty * 8 + i;
        if (row < M) {
            __half2 h01 = __floats2half2_rn(acc[i][0], acc[i][1]);
            __half2 h23 = __floats2half2_rn(acc[i][2], acc[i][3]);
            uint2 u;
            u.x = *(unsigned*)&h01;
            u.y = *(unsigned*)&h23;
            *(uint2*)&C[(size_t)row * N + bn + tx * 4] = u;   // 8B aligned
        }
    }
    if (H > 0) {
        const int hd = bn >> 6;
        float asr[4], adr[4];
        #pragma unroll
        for (int j = 0; j < 4; j++) {
            asr[j] = a_src[bn + tx * 4 + j];
            adr[j] = a_dst[bn + tx * 4 + j];
        }
        #pragma unroll
        for (int i = 0; i < 8; i++) {
            float s = 0.f, d = 0.f;
            #pragma unroll
            for (int j = 0; j < 4; j++) {
                s = fmaf(acc[i][j], asr[j], s);
                d = fmaf(acc[i][j], adr[j], d);
            }
            #pragma unroll
            for (int off = 8; off >= 1; off >>= 1) {
                s += __shfl_xor_sync(0xffffffffu, s, off);
                d += __shfl_xor_sync(0xffffffffu, d, off);
            }
            int row = bm + ty * 8 + i;
            if (tx == 0 && row < M) {
                g_als[row * H + hd] = s;
                g_ald[row * H + hd] = d;
            }
        }
    }
}

// ---------------------------------------------------------------------------
// CSR build (dst-indexed, real edges only; self-loops handled inline later)
// ---------------------------------------------------------------------------
__global__ void degi_kernel(const int* __restrict__ dst, int E) {
    int i = blockIdx.x * blockDim.x + threadIdx.x;
    if (i < E) atomicAdd(&g_degi[dst[i]], 1);
}

__global__ void scan_reduce_kernel(int n) {
    __shared__ int red[512];
    const int b = blockIdx.x, t = threadIdx.x;
    const int base = b * SCAN_CHUNK;
    int s = 0;
    #pragma unroll
    for (int i = t; i < SCAN_CHUNK; i += 512) {
        int idx = base + i;
        if (idx < n) s += g_degi[idx];
    }
    red[t] = s;
    __syncthreads();
    #pragma unroll
    for (int off = 256; off > 0; off >>= 1) {
        if (t < off) red[t] += red[t + off];
        __syncthreads();
    }
    if (t == 0) g_bsum[b] = red[0];
}

// per-block scan via warp shuffles (2 barriers); block offset inline (nb<=13)
__global__ void scan_write_kernel(int n) {
    __shared__ int wsum[16];
    const int b = blockIdx.x, t = threadIdx.x;
    const int lane = t & 31, wid = t >> 5;
    const int start = b * SCAN_CHUNK + t * 8;
    int vals[8];
    int s = 0;
    #pragma unroll
    for (int i = 0; i < 8; i++) {
        int idx = start + i;
        vals[i] = (idx < n) ? g_degi[idx] : 0;
        s += vals[i];
    }
    int ps = s;
    #pragma unroll
    for (int off = 1; off < 32; off <<= 1) {
        int v = __shfl_up_sync(0xffffffffu, ps, off);
        if (lane >= off) ps += v;
    }
    if (lane == 31) wsum[wid] = ps;
    __syncthreads();
    if (wid == 0 && lane < 16) {
        int v = wsum[lane];
        #pragma unroll
        for (int off = 1; off < 16; off <<= 1) {
            int u = __shfl_up_sync(0x0000ffffu, v, off);
            if (lane >= off) v += u;
        }
        wsum[lane] = v;
    }
    __syncthreads();
    int boff = 0;
    for (int i = 0; i < b; i++) boff += g_bsum[i];
    int excl = boff + ((wid > 0) ? wsum[wid - 1] : 0) + (ps - s);
    #pragma unroll
    for (int i = 0; i < 8; i++) {
        int idx = start + i;
        if (idx < n) {
            g_rowptr[idx] = excl;
            g_cursor[idx] = excl;
            g_dis[idx] = rsqrtf((float)(vals[i] + 1));  // +1 self-loop
            excl += vals[i];
            if (idx == n - 1) g_rowptr[n] = excl;
        }
    }
}

__global__ void csr_fill_kernel(const int* __restrict__ src,
                                const int* __restrict__ dst, int E) {
    int e = blockIdx.x * blockDim.x + threadIdx.x;
    if (e >= E) return;
    int pos = atomicAdd(&g_cursor[dst[e]], 1);
    g_col[pos] = src[e];
}

// ---------------------------------------------------------------------------
// GCN aggregation: warp per node, smem-staged edges, fp16 feature gathers.
// ---------------------------------------------------------------------------
__global__ void gcn_gather_kernel(const float* __restrict__ b1, int n) {
    __shared__ int   s_col[8][32];
    __shared__ float s_wt[8][32];
    const int w = (blockIdx.x * blockDim.x + threadIdx.x) >> 5;
    const int lane = threadIdx.x & 31;
    const int wrp = threadIdx.x >> 5;
    if (w >= n) return;
    const int d = w;
    const float dd = g_dis[d];
    const float2 sv = __half22float2(*(const __half2*)&g_bufA[(size_t)d * 64 + lane * 2]);
    float ax = dd * dd * sv.x;
    float ay = dd * dd * sv.y;
    const int beg = g_rowptr[d], end = g_rowptr[d + 1];

    auto proc = [&](int k) {
        int s = s_col[wrp][k];
        float ws = s_wt[wrp][k];
        const float2 v = __half22float2(*(const __half2*)&g_bufA[(size_t)s * 64 + lane * 2]);
        ax = fmaf(ws, v.x, ax);
        ay = fmaf(ws, v.y, ay);
    };

    for (int j0 = beg; j0 < end; j0 += 32) {
        const int cnt = min(32, end - j0);
        if (lane < cnt) {
            int s = g_col[j0 + lane];
            s_col[wrp][lane] = s;
            s_wt[wrp][lane] = g_dis[s] * dd;
        }
        __syncwarp();
        int k = 0;
        for (; k + 4 <= cnt; k += 4) { proc(k); proc(k + 1); proc(k + 2); proc(k + 3); }
        for (; k < cnt; k++) proc(k);
        __syncwarp();
    }
    ax += b1[lane * 2];
    ay += b1[lane * 2 + 1];
    float2 o;
    o.x = ax > 0.0f ? ax : 0.0f;
    o.y = ay > 0.0f ? ay : 0.0f;
    *(float2*)&g_bufB[(size_t)d * 64 + lane * 2] = o;
}

// ---------------------------------------------------------------------------
// GAT aggregation: warp per node, smem-staged edges, chunk-max online
// softmax, owner-lane exp, fp16 feature gathers.
// ---------------------------------------------------------------------------
template <int H, int F, bool RELU>
__global__ void gat_gather_kernel(const float* __restrict__ bias, int n,
                                  float* __restrict__ out) {
    constexpr int HF = H * F;
    constexpr int VPL = HF / 32;          // values per lane (2 or 4)
    __shared__ int   s_col[8][32];
    __shared__ float s_e[8][H * 32];      // staged logits -> exps (in-place)
    const int w = (blockIdx.x * blockDim.x + threadIdx.x) >> 5;
    const int lane = threadIdx.x & 31;
    const int wrp = threadIdx.x >> 5;
    if (w >= n) return;
    const int d = w;
    const int hd = (lane * VPL) / F;      // this lane's head

    float ald_d[H], m[H], l[H];
    #pragma unroll
    for (int h = 0; h < H; h++) {
        ald_d[h] = g_ald[d * H + h];
        float v = g_als[d * H + h] + ald_d[h];
        v = v > 0.0f ? v : 0.2f * v;      // leaky relu
        m[h] = v;
        l[h] = 1.0f;
    }

    // fp16 feature loader: VPL values from node s at this lane's slice
    auto loadf = [&](int s, float (&v)[VPL]) {
        if (VPL == 4) {
            uint2 u = *(const uint2*)&g_bufA[(size_t)s * HF + lane * 4];  // 8B aligned
            float2 v01 = __half22float2(*(__half2*)&u.x);
            float2 v23 = __half22float2(*(__half2*)&u.y);
            v[0] = v01.x; v[1] = v01.y; v[2] = v23.x; v[3] = v23.y;
        } else {
            float2 v01 = __half22float2(*(const __half2*)&g_bufA[(size_t)s * HF + lane * 2]);
            v[0] = v01.x; v[1] = v01.y;
        }
    };

    // self-loop contribution (exp(v - m) = 1 at init)
    float acc[VPL];
    loadf(d, acc);

    const int beg = g_rowptr[d], end = g_rowptr[d + 1];

    auto proc = [&](int k) {
        int s = s_col[wrp][k];
        float ex0 = s_e[wrp][k];          // already exponentiated
        l[0] += ex0;
        float ee = ex0;
        if (H == 2) {
            float ex1 = s_e[wrp][32 + k];
            l[1] += ex1;
            if (hd == 1) ee = ex1;
        }
        float v[VPL];
        loadf(s, v);
        #pragma unroll
        for (int i = 0; i < VPL; i++) acc[i] = fmaf(ee, v[i], acc[i]);
    };

    for (int j0 = beg; j0 < end; j0 += 32) {
        const int cnt = min(32, end - j0);
        float myv[H];
        #pragma unroll
        for (int h = 0; h < H; h++) myv[h] = -3.0e38f;
        if (lane < cnt) {
            int s = g_col[j0 + lane];
            s_col[wrp][lane] = s;
            #pragma unroll
            for (int h = 0; h < H; h++) {
                float v = g_als[s * H + h] + ald_d[h];
                v = v > 0.0f ? v : 0.2f * v;
                myv[h] = v;
            }
        }
        // chunk max per head + single rescale (m warp-uniform afterwards)
        #pragma unroll
        for (int h = 0; h < H; h++) {
            float cm = myv[h];
            #pragma unroll
            for (int off = 16; off >= 1; off >>= 1)
                cm = fmaxf(cm, __shfl_xor_sync(0xffffffffu, cm, off));
            if (cm > m[h]) {
                float r = __expf(m[h] - cm);
                l[h] *= r;
                if (h == ((H == 2) ? hd : 0)) {
                    #pragma unroll
                    for (int i = 0; i < VPL; i++) acc[i] *= r;
                }
                m[h] = cm;
            }
        }
        // owner-lane exponentiation: one MUFU per edge-head for the warp
        if (lane < cnt) {
            #pragma unroll
            for (int h = 0; h < H; h++)
                s_e[wrp][h * 32 + lane] = __expf(myv[h] - m[h]);
        }
        __syncwarp();
        int k = 0;
        for (; k + 4 <= cnt; k += 4) { proc(k); proc(k + 1); proc(k + 2); proc(k + 3); }
        for (; k < cnt; k++) proc(k);
        __syncwarp();
    }

    const float inv = 1.0f / ((H == 2 && hd == 1) ? l[1] : l[0]);
    #pragma unroll
    for (int i = 0; i < VPL; i++) {
        float v = acc[i] * inv + bias[lane * VPL + i];
        if (RELU) v = v > 0.0f ? v : 0.0f;
        acc[i] = v;
    }
    float* op = &out[(size_t)d * HF + lane * VPL];
    if (VPL == 4) {
        float4 o; o.x = acc[0]; o.y = acc[1]; o.z = acc[2]; o.w = acc[3];
        *(float4*)op = o;
    } else {
        float2 o; o.x = acc[0]; o.y = acc[1];
        *(float2*)op = o;
    }
}

// ---------------------------------------------------------------------------
// Pooling + classifier
// ---------------------------------------------------------------------------
__global__ void pool_kernel(const int* __restrict__ batch, int n) {
    int t = blockIdx.x * blockDim.x + threadIdx.x;
    int node = t >> 4, lane = t & 15;
    if (node >= n) return;
    int g = batch[node];
    const float4 v = *(const float4*)&g_bufB[(size_t)node * 64 + lane * 4];
    float* o = &g_sums[g * 64 + lane * 4];
    atomicAdd(o + 0, v.x);
    atomicAdd(o + 1, v.y);
    atomicAdd(o + 2, v.z);
    atomicAdd(o + 3, v.w);
    if (lane == 0) atomicAdd(&g_cnt[g], 1.0f);
}

__global__ void final_kernel(const float* __restrict__ Wfc, const float* __restrict__ bfc,
                             float* __restrict__ out, int G) {
    int g = blockIdx.x * blockDim.x + threadIdx.x;
    if (g >= G) return;
    float c = fmaxf(g_cnt[g], 1.0f);
    float l0 = bfc[0], l1 = bfc[1];
    #pragma unroll
    for (int f = 0; f < 64; f++) {
        float p = g_sums[g * 64 + f] / c;
        l0 = fmaf(p, Wfc[f * 2 + 0], l0);
        l1 = fmaf(p, Wfc[f * 2 + 1], l1);
    }
    float m = fmaxf(l0, l1);
    float lse = m + logf(expf(l0 - m) + expf(l1 - m));
    out[2 * g + 0] = l0 - lse;
    out[2 * g + 1] = l1 - lse;
}

// ---------------------------------------------------------------------------
// Host launcher
// ---------------------------------------------------------------------------
extern "C" void kernel_launch(void* const* d_in, const int* in_sizes, int n_in,
                              void* d_out, int out_size) {
    const float* x    = (const float*)d_in[0];
    const int*   ei   = (const int*)d_in[1];
    const int*   bat  = (const int*)d_in[2];
    const float* W1   = (const float*)d_in[3];
    const float* b1   = (const float*)d_in[4];
    const float* W2   = (const float*)d_in[5];
    const float* as2  = (const float*)d_in[6];
    const float* ad2  = (const float*)d_in[7];
    const float* b2   = (const float*)d_in[8];
    const float* W3   = (const float*)d_in[9];
    const float* as3  = (const float*)d_in[10];
    const float* ad3  = (const float*)d_in[11];
    const float* b3   = (const float*)d_in[12];
    const float* Wfc  = (const float*)d_in[13];
    const float* bfc  = (const float*)d_in[14];

    const int n  = in_sizes[0] / 128;   // 50000
    const int E  = in_sizes[1] / 2;     // 800000
    const int G  = out_size / 2;        // 512
    const int* src = ei;
    const int* dst = ei + E;
    const int nb = (n + SCAN_CHUNK - 1) / SCAN_CHUNK;

    void *pBufA, *pBufB, *pDegi, *pSums, *pCnt;
    cudaGetSymbolAddress(&pBufA, g_bufA);
    cudaGetSymbolAddress(&pBufB, g_bufB);
    cudaGetSymbolAddress(&pDegi, g_degi);
    cudaGetSymbolAddress(&pSums, g_sums);
    cudaGetSymbolAddress(&pCnt,  g_cnt);

    const int TB = 256;
    auto cdiv = [](long long a, long long b) { return (int)((a + b - 1) / b); };
    cudaStream_t s2 = g_side.s;

    // ===== Fork: CSR build on side stream, GEMM1 on main stream =====
    cudaEventRecord(g_side.fork, 0);
    cudaStreamWaitEvent(s2, g_side.fork, 0);

    cudaMemsetAsync(pDegi, 0, (size_t)n * sizeof(int), s2);
    cudaMemsetAsync(pSums, 0, (size_t)G * 64 * sizeof(float), s2);
    cudaMemsetAsync(pCnt,  0, (size_t)G * sizeof(float), s2);
    degi_kernel<<<cdiv(E, TB), TB, 0, s2>>>(dst, E);
    scan_reduce_kernel<<<nb, 512, 0, s2>>>(n);
    scan_write_kernel<<<nb, 512, 0, s2>>>(n);
    csr_fill_kernel<<<cdiv(E, TB), TB, 0, s2>>>(src, dst, E);
    cudaEventRecord(g_side.join, s2);

    sgemm_kernel<0><<<dim3(1, cdiv(n, 128)), TB>>>(x, W1, (__half*)pBufA, n, 64, 128, nullptr, nullptr);

    // ===== Join, then layer 1: GCNConv(128 -> 64) + relu (fused) =====
    cudaStreamWaitEvent(0, g_side.join, 0);
    gcn_gather_kernel<<<cdiv((long long)n * 32, TB), TB>>>(b1, n);

    // ===== Layer 2: GATConv(64 -> 64, heads=2, concat) + relu =====
    sgemm_kernel<2><<<dim3(2, cdiv(n, 128)), TB>>>((const float*)pBufB, W2, (__half*)pBufA, n, 128, 64, as2, ad2);
    gat_gather_kernel<2, 64, true><<<cdiv((long long)n * 32, TB), TB>>>(b2, n, (float*)pBufB);

    // ===== Layer 3: GATConv(128 -> 64, heads=1, mean) =====
    sgemm_kernel<1><<<dim3(1, cdiv(n, 128)), TB>>>((const float*)pBufB, W3, (__half*)pBufA, n, 64, 128, as3, ad3);
    gat_gather_kernel<1, 64, false><<<cdiv((long long)n * 32, TB), TB>>>(b3, n, (float*)pBufB);

    // ===== Mean pool + FC + log_softmax =====
    pool_kernel<<<cdiv((long long)n * 16, TB), TB>>>(bat, n);
    final_kernel<<<cdiv(G, TB), TB>>>(Wfc, bfc, (float*)d_out, G);
}

// round 16
// speedup vs baseline: 1.3516x; 1.0866x over previous
#include <cuda_runtime.h>
#include <cuda_fp16.h>
#include <mma.h>
#include <cstdint>

using namespace nvcuda;

// ---------------------------------------------------------------------------
// Problem constants (shapes fixed by the dataset)
// ---------------------------------------------------------------------------
#define MAXN 50048            // >= N=50000
#define MAXE 800000
#define MAXG 512
#define SCAN_CHUNK 4096       // elements per scan block (512 thr * 8)
#define MAXSB ((MAXN + SCAN_CHUNK - 1) / SCAN_CHUNK)

// ---------------------------------------------------------------------------
// Device scratch (static allocation — no cudaMalloc allowed)
// ---------------------------------------------------------------------------
__device__ __align__(16) __half g_bufA[(size_t)MAXN * 128]; // GEMM outputs (fp16 features)
__device__ __align__(16) __half g_bufB[(size_t)MAXN * 128]; // layer outputs (fp16, GEMM inputs)
__device__ __align__(16) __half g_x16[(size_t)MAXN * 128];  // fp16 copy of input x
__device__ __align__(16) __half g_w1h[128 * 64];
__device__ __align__(16) __half g_w2h[64 * 128];
__device__ __align__(16) __half g_w3h[128 * 64];
__device__ int   g_degi[MAXN];
__device__ int   g_rowptr[MAXN + 1];
__device__ int   g_cursor[MAXN];
__device__ int   g_col[MAXE];
__device__ int   g_bsum[MAXSB];
__device__ float g_dis[MAXN];
__device__ __align__(8) float g_als[MAXN * 2];
__device__ __align__(8) float g_ald[MAXN * 2];
__device__ __align__(16) float g_sums[MAXG * 64];
__device__ float g_cnt[MAXG];

// ---------------------------------------------------------------------------
// Side stream + events for fork/join inside graph capture (created once at
// process init; kernel_launch itself performs identical work every call).
// ---------------------------------------------------------------------------
struct SideStream {
    cudaStream_t s;
    cudaEvent_t fork, join;
    SideStream() {
        cudaStreamCreateWithFlags(&s, cudaStreamNonBlocking);
        cudaEventCreateWithFlags(&fork, cudaEventDisableTiming);
        cudaEventCreateWithFlags(&join, cudaEventDisableTiming);
    }
};
static SideStream g_side;

// ---------------------------------------------------------------------------
// fp32 -> fp16 conversion (2 elems / thread)
// ---------------------------------------------------------------------------
__global__ void cvt_kernel(const float* __restrict__ src, __half* __restrict__ dst,
                           int n2) {
    int i = blockIdx.x * blockDim.x + threadIdx.x;
    if (i < n2) {
        float2 v = *(const float2*)&src[i * 2];
        *(__half2*)&dst[i * 2] = __floats2half2_rn(v.x, v.y);
    }
}

// ---------------------------------------------------------------------------
// Tensor-core HGEMM: C[M,N] = A[M,K] @ B[K,N], fp16 in, fp32 accum, fp16 out.
// BM=64, BN=64, BK=16; 256 thr = 8 warps (4 m x 2 n), 2 frags / warp.
// H > 0: fused GAT attention-logit epilogue (64-col block == one head).
// ---------------------------------------------------------------------------
template <int H>
__global__ void hgemm_kernel(const __half* __restrict__ A, const __half* __restrict__ B,
                             __half* __restrict__ C, int M, int N, int K,
                             const float* __restrict__ a_src,
                             const float* __restrict__ a_dst) {
    __shared__ __half As[64][24];   // stride 48B (16B mult)
    __shared__ __half Bs[16][72];   // stride 144B (16B mult)
    __shared__ float  Cs[64][68];   // stride 272B (16B mult)
    const int bm = blockIdx.y * 64;
    const int bn = blockIdx.x * 64;
    const int tid = threadIdx.x;
    const int lane = tid & 31;
    const int warp = tid >> 5;
    const int wm = warp & 3;        // 0..3 -> 16-row slice
    const int wn = warp >> 2;       // 0..1 -> 32-col slice

    wmma::fragment<wmma::accumulator, 16, 16, 16, float> facc[2];
    wmma::fill_fragment(facc[0], 0.0f);
    wmma::fill_fragment(facc[1], 0.0f);

    for (int k0 = 0; k0 < K; k0 += 16) {
        // A tile 64x16: thread -> (row=tid>>2, 4 halves at (tid&3)*4)
        {
            int r = tid >> 2, c4 = (tid & 3) * 4;
            int row = bm + r;
            uint2 v = make_uint2(0u, 0u);
            if (row < M) v = *(const uint2*)&A[(size_t)row * K + k0 + c4];
            *(uint2*)&As[r][c4] = v;
        }
        // B tile 16x64: thread -> (row=tid>>4, 4 halves at (tid&15)*4)
        {
            int r = tid >> 4, c4 = (tid & 15) * 4;
            uint2 v = *(const uint2*)&B[(size_t)(k0 + r) * N + bn + c4];
            *(uint2*)&Bs[r][c4] = v;
        }
        __syncthreads();
        wmma::fragment<wmma::matrix_a, 16, 16, 16, __half, wmma::row_major> fa;
        wmma::load_matrix_sync(fa, &As[wm * 16][0], 24);
        #pragma unroll
        for (int f = 0; f < 2; f++) {
            wmma::fragment<wmma::matrix_b, 16, 16, 16, __half, wmma::row_major> fb;
            wmma::load_matrix_sync(fb, &Bs[0][wn * 32 + f * 16], 72);
            wmma::mma_sync(facc[f], fa, fb, facc[f]);
        }
        __syncthreads();
    }
    // accumulators -> smem fp32
    wmma::store_matrix_sync(&Cs[wm * 16][wn * 32], facc[0], 68, wmma::mem_row_major);
    wmma::store_matrix_sync(&Cs[wm * 16][wn * 32 + 16], facc[1], 68, wmma::mem_row_major);
    __syncthreads();

    // epilogue: thread -> (row=tid>>2, 16-col segment seg=tid&3)
    {
        const int r = tid >> 2, seg = tid & 3;
        const int row = bm + r;
        float c[16];
        #pragma unroll
        for (int j = 0; j < 16; j++) c[j] = Cs[r][seg * 16 + j];
        if (row < M) {
            __half hv[16];
            #pragma unroll
            for (int j = 0; j < 16; j++) hv[j] = __float2half(c[j]);
            uint4* dst = (uint4*)&C[(size_t)row * N + bn + seg * 16];
            dst[0] = *(uint4*)&hv[0];
            dst[1] = *(uint4*)&hv[8];
        }
        if (H > 0) {
            float s = 0.f, d = 0.f;
            #pragma unroll
            for (int j = 0; j < 16; j++) {
                float a = a_src[bn + seg * 16 + j];
                float b = a_dst[bn + seg * 16 + j];
                s = fmaf(c[j], a, s);
                d = fmaf(c[j], b, d);
            }
            // reduce across the 4 segment lanes (same quad within warp)
            #pragma unroll
            for (int off = 2; off >= 1; off >>= 1) {
                s += __shfl_xor_sync(0xffffffffu, s, off);
                d += __shfl_xor_sync(0xffffffffu, d, off);
            }
            if (seg == 0 && row < M) {
                const int hd = bn >> 6;
                g_als[row * H + hd] = s;
                g_ald[row * H + hd] = d;
            }
        }
    }
}

// ---------------------------------------------------------------------------
// CSR build (dst-indexed, real edges only; self-loops handled inline later)
// ---------------------------------------------------------------------------
__global__ void degi_kernel(const int* __restrict__ dst, int E) {
    int i = blockIdx.x * blockDim.x + threadIdx.x;
    if (i < E) atomicAdd(&g_degi[dst[i]], 1);
}

__global__ void scan_reduce_kernel(int n) {
    __shared__ int red[512];
    const int b = blockIdx.x, t = threadIdx.x;
    const int base = b * SCAN_CHUNK;
    int s = 0;
    #pragma unroll
    for (int i = t; i < SCAN_CHUNK; i += 512) {
        int idx = base + i;
        if (idx < n) s += g_degi[idx];
    }
    red[t] = s;
    __syncthreads();
    #pragma unroll
    for (int off = 256; off > 0; off >>= 1) {
        if (t < off) red[t] += red[t + off];
        __syncthreads();
    }
    if (t == 0) g_bsum[b] = red[0];
}

// per-block scan via warp shuffles (2 barriers); block offset inline (nb<=13)
__global__ void scan_write_kernel(int n) {
    __shared__ int wsum[16];
    const int b = blockIdx.x, t = threadIdx.x;
    const int lane = t & 31, wid = t >> 5;
    const int start = b * SCAN_CHUNK + t * 8;
    int vals[8];
    int s = 0;
    #pragma unroll
    for (int i = 0; i < 8; i++) {
        int idx = start + i;
        vals[i] = (idx < n) ? g_degi[idx] : 0;
        s += vals[i];
    }
    int ps = s;
    #pragma unroll
    for (int off = 1; off < 32; off <<= 1) {
        int v = __shfl_up_sync(0xffffffffu, ps, off);
        if (lane >= off) ps += v;
    }
    if (lane == 31) wsum[wid] = ps;
    __syncthreads();
    if (wid == 0 && lane < 16) {
        int v = wsum[lane];
        #pragma unroll
        for (int off = 1; off < 16; off <<= 1) {
            int u = __shfl_up_sync(0x0000ffffu, v, off);
            if (lane >= off) v += u;
        }
        wsum[lane] = v;
    }
    __syncthreads();
    int boff = 0;
    for (int i = 0; i < b; i++) boff += g_bsum[i];
    int excl = boff + ((wid > 0) ? wsum[wid - 1] : 0) + (ps - s);
    #pragma unroll
    for (int i = 0; i < 8; i++) {
        int idx = start + i;
        if (idx < n) {
            g_rowptr[idx] = excl;
            g_cursor[idx] = excl;
            g_dis[idx] = rsqrtf((float)(vals[i] + 1));  // +1 self-loop
            excl += vals[i];
            if (idx == n - 1) g_rowptr[n] = excl;
        }
    }
}

__global__ void csr_fill_kernel(const int* __restrict__ src,
                                const int* __restrict__ dst, int E) {
    int e = blockIdx.x * blockDim.x + threadIdx.x;
    if (e >= E) return;
    int pos = atomicAdd(&g_cursor[dst[e]], 1);
    g_col[pos] = src[e];
}

// ---------------------------------------------------------------------------
// GCN aggregation: warp per node, smem-staged edges, fp16 gathers, fp16 out.
// ---------------------------------------------------------------------------
__global__ void gcn_gather_kernel(const float* __restrict__ b1, int n) {
    __shared__ int   s_col[8][32];
    __shared__ float s_wt[8][32];
    const int w = (blockIdx.x * blockDim.x + threadIdx.x) >> 5;
    const int lane = threadIdx.x & 31;
    const int wrp = threadIdx.x >> 5;
    if (w >= n) return;
    const int d = w;
    const float dd = g_dis[d];
    const float2 sv = __half22float2(*(const __half2*)&g_bufA[(size_t)d * 64 + lane * 2]);
    float ax = dd * dd * sv.x;
    float ay = dd * dd * sv.y;
    const int beg = g_rowptr[d], end = g_rowptr[d + 1];

    auto proc = [&](int k) {
        int s = s_col[wrp][k];
        float ws = s_wt[wrp][k];
        const float2 v = __half22float2(*(const __half2*)&g_bufA[(size_t)s * 64 + lane * 2]);
        ax = fmaf(ws, v.x, ax);
        ay = fmaf(ws, v.y, ay);
    };

    for (int j0 = beg; j0 < end; j0 += 32) {
        const int cnt = min(32, end - j0);
        if (lane < cnt) {
            int s = g_col[j0 + lane];
            s_col[wrp][lane] = s;
            s_wt[wrp][lane] = g_dis[s] * dd;
        }
        __syncwarp();
        int k = 0;
        for (; k + 4 <= cnt; k += 4) { proc(k); proc(k + 1); proc(k + 2); proc(k + 3); }
        for (; k < cnt; k++) proc(k);
        __syncwarp();
    }
    ax += b1[lane * 2];
    ay += b1[lane * 2 + 1];
    ax = ax > 0.0f ? ax : 0.0f;
    ay = ay > 0.0f ? ay : 0.0f;
    *(__half2*)&g_bufB[(size_t)d * 64 + lane * 2] = __floats2half2_rn(ax, ay);
}

// ---------------------------------------------------------------------------
// GAT aggregation: warp per node, smem-staged edges, chunk-max online
// softmax, owner-lane exp, fp16 gathers, fp16 out.
// ---------------------------------------------------------------------------
template <int H, int F, bool RELU>
__global__ void gat_gather_kernel(const float* __restrict__ bias, int n,
                                  __half* __restrict__ out) {
    constexpr int HF = H * F;
    constexpr int VPL = HF / 32;          // values per lane (2 or 4)
    __shared__ int   s_col[8][32];
    __shared__ float s_e[8][H * 32];      // staged logits -> exps (in-place)
    const int w = (blockIdx.x * blockDim.x + threadIdx.x) >> 5;
    const int lane = threadIdx.x & 31;
    const int wrp = threadIdx.x >> 5;
    if (w >= n) return;
    const int d = w;
    const int hd = (lane * VPL) / F;      // this lane's head

    float ald_d[H], m[H], l[H];
    #pragma unroll
    for (int h = 0; h < H; h++) {
        ald_d[h] = g_ald[d * H + h];
        float v = g_als[d * H + h] + ald_d[h];
        v = v > 0.0f ? v : 0.2f * v;      // leaky relu
        m[h] = v;
        l[h] = 1.0f;
    }

    auto loadf = [&](int s, float (&v)[VPL]) {
        if (VPL == 4) {
            uint2 u = *(const uint2*)&g_bufA[(size_t)s * HF + lane * 4];
            float2 v01 = __half22float2(*(__half2*)&u.x);
            float2 v23 = __half22float2(*(__half2*)&u.y);
            v[0] = v01.x; v[1] = v01.y; v[2] = v23.x; v[3] = v23.y;
        } else {
            float2 v01 = __half22float2(*(const __half2*)&g_bufA[(size_t)s * HF + lane * 2]);
            v[0] = v01.x; v[1] = v01.y;
        }
    };

    // self-loop contribution (exp(v - m) = 1 at init)
    float acc[VPL];
    loadf(d, acc);

    const int beg = g_rowptr[d], end = g_rowptr[d + 1];

    auto proc = [&](int k) {
        int s = s_col[wrp][k];
        float ex0 = s_e[wrp][k];
        l[0] += ex0;
        float ee = ex0;
        if (H == 2) {
            float ex1 = s_e[wrp][32 + k];
            l[1] += ex1;
            if (hd == 1) ee = ex1;
        }
        float v[VPL];
        loadf(s, v);
        #pragma unroll
        for (int i = 0; i < VPL; i++) acc[i] = fmaf(ee, v[i], acc[i]);
    };

    for (int j0 = beg; j0 < end; j0 += 32) {
        const int cnt = min(32, end - j0);
        float myv[H];
        #pragma unroll
        for (int h = 0; h < H; h++) myv[h] = -3.0e38f;
        if (lane < cnt) {
            int s = g_col[j0 + lane];
            s_col[wrp][lane] = s;
            #pragma unroll
            for (int h = 0; h < H; h++) {
                float v = g_als[s * H + h] + ald_d[h];
                v = v > 0.0f ? v : 0.2f * v;
                myv[h] = v;
            }
        }
        #pragma unroll
        for (int h = 0; h < H; h++) {
            float cm = myv[h];
            #pragma unroll
            for (int off = 16; off >= 1; off >>= 1)
                cm = fmaxf(cm, __shfl_xor_sync(0xffffffffu, cm, off));
            if (cm > m[h]) {
                float r = __expf(m[h] - cm);
                l[h] *= r;
                if (h == ((H == 2) ? hd : 0)) {
                    #pragma unroll
                    for (int i = 0; i < VPL; i++) acc[i] *= r;
                }
                m[h] = cm;
            }
        }
        if (lane < cnt) {
            #pragma unroll
            for (int h = 0; h < H; h++)
                s_e[wrp][h * 32 + lane] = __expf(myv[h] - m[h]);
        }
        __syncwarp();
        int k = 0;
        for (; k + 4 <= cnt; k += 4) { proc(k); proc(k + 1); proc(k + 2); proc(k + 3); }
        for (; k < cnt; k++) proc(k);
        __syncwarp();
    }

    const float inv = 1.0f / ((H == 2 && hd == 1) ? l[1] : l[0]);
    #pragma unroll
    for (int i = 0; i < VPL; i++) {
        float v = acc[i] * inv + bias[lane * VPL + i];
        if (RELU) v = v > 0.0f ? v : 0.0f;
        acc[i] = v;
    }
    __half* op = &out[(size_t)d * HF + lane * VPL];
    if (VPL == 4) {
        __half2 h01 = __floats2half2_rn(acc[0], acc[1]);
        __half2 h23 = __floats2half2_rn(acc[2], acc[3]);
        uint2 u;
        u.x = *(unsigned*)&h01;
        u.y = *(unsigned*)&h23;
        *(uint2*)op = u;
    } else {
        *(__half2*)op = __floats2half2_rn(acc[0], acc[1]);
    }
}

// ---------------------------------------------------------------------------
// Pooling + classifier (pool reads fp16 layer-3 output)
// ---------------------------------------------------------------------------
__global__ void pool_kernel(const int* __restrict__ batch, int n) {
    int t = blockIdx.x * blockDim.x + threadIdx.x;
    int node = t >> 4, lane = t & 15;
    if (node >= n) return;
    int g = batch[node];
    uint2 u = *(const uint2*)&g_bufB[(size_t)node * 64 + lane * 4];
    float2 v01 = __half22float2(*(__half2*)&u.x);
    float2 v23 = __half22float2(*(__half2*)&u.y);
    float* o = &g_sums[g * 64 + lane * 4];
    atomicAdd(o + 0, v01.x);
    atomicAdd(o + 1, v01.y);
    atomicAdd(o + 2, v23.x);
    atomicAdd(o + 3, v23.y);
    if (lane == 0) atomicAdd(&g_cnt[g], 1.0f);
}

__global__ void final_kernel(const float* __restrict__ Wfc, const float* __restrict__ bfc,
                             float* __restrict__ out, int G) {
    int g = blockIdx.x * blockDim.x + threadIdx.x;
    if (g >= G) return;
    float c = fmaxf(g_cnt[g], 1.0f);
    float l0 = bfc[0], l1 = bfc[1];
    #pragma unroll
    for (int f = 0; f < 64; f++) {
        float p = g_sums[g * 64 + f] / c;
        l0 = fmaf(p, Wfc[f * 2 + 0], l0);
        l1 = fmaf(p, Wfc[f * 2 + 1], l1);
    }
    float m = fmaxf(l0, l1);
    float lse = m + logf(expf(l0 - m) + expf(l1 - m));
    out[2 * g + 0] = l0 - lse;
    out[2 * g + 1] = l1 - lse;
}

// ---------------------------------------------------------------------------
// Host launcher
// ---------------------------------------------------------------------------
extern "C" void kernel_launch(void* const* d_in, const int* in_sizes, int n_in,
                              void* d_out, int out_size) {
    const float* x    = (const float*)d_in[0];
    const int*   ei   = (const int*)d_in[1];
    const int*   bat  = (const int*)d_in[2];
    const float* W1   = (const float*)d_in[3];
    const float* b1   = (const float*)d_in[4];
    const float* W2   = (const float*)d_in[5];
    const float* as2  = (const float*)d_in[6];
    const float* ad2  = (const float*)d_in[7];
    const float* b2   = (const float*)d_in[8];
    const float* W3   = (const float*)d_in[9];
    const float* as3  = (const float*)d_in[10];
    const float* ad3  = (const float*)d_in[11];
    const float* b3   = (const float*)d_in[12];
    const float* Wfc  = (const float*)d_in[13];
    const float* bfc  = (const float*)d_in[14];

    const int n  = in_sizes[0] / 128;   // 50000
    const int E  = in_sizes[1] / 2;     // 800000
    const int G  = out_size / 2;        // 512
    const int* src = ei;
    const int* dst = ei + E;
    const int nb = (n + SCAN_CHUNK - 1) / SCAN_CHUNK;

    void *pBufA, *pBufB, *pX16, *pW1h, *pW2h, *pW3h, *pDegi, *pSums, *pCnt;
    cudaGetSymbolAddress(&pBufA, g_bufA);
    cudaGetSymbolAddress(&pBufB, g_bufB);
    cudaGetSymbolAddress(&pX16,  g_x16);
    cudaGetSymbolAddress(&pW1h,  g_w1h);
    cudaGetSymbolAddress(&pW2h,  g_w2h);
    cudaGetSymbolAddress(&pW3h,  g_w3h);
    cudaGetSymbolAddress(&pDegi, g_degi);
    cudaGetSymbolAddress(&pSums, g_sums);
    cudaGetSymbolAddress(&pCnt,  g_cnt);

    const int TB = 256;
    auto cdiv = [](long long a, long long b) { return (int)((a + b - 1) / b); };
    cudaStream_t s2 = g_side.s;

    // ===== Fork: CSR build on side stream =====
    cudaEventRecord(g_side.fork, 0);
    cudaStreamWaitEvent(s2, g_side.fork, 0);

    cudaMemsetAsync(pDegi, 0, (size_t)n * sizeof(int), s2);
    cudaMemsetAsync(pSums, 0, (size_t)G * 64 * sizeof(float), s2);
    cudaMemsetAsync(pCnt,  0, (size_t)G * sizeof(float), s2);
    degi_kernel<<<cdiv(E, TB), TB, 0, s2>>>(dst, E);
    scan_reduce_kernel<<<nb, 512, 0, s2>>>(n);
    scan_write_kernel<<<nb, 512, 0, s2>>>(n);
    csr_fill_kernel<<<cdiv(E, TB), TB, 0, s2>>>(src, dst, E);
    cudaEventRecord(g_side.join, s2);

    // ===== Main: fp16 conversions, then GEMM1 =====
    cvt_kernel<<<cdiv((long long)n * 64, TB), TB>>>(x, (__half*)pX16, n * 64);
    cvt_kernel<<<cdiv(128 * 32, TB), TB>>>(W1, (__half*)pW1h, 128 * 32);
    cvt_kernel<<<cdiv(64 * 64, TB), TB>>>(W2, (__half*)pW2h, 64 * 64);
    cvt_kernel<<<cdiv(128 * 32, TB), TB>>>(W3, (__half*)pW3h, 128 * 32);

    hgemm_kernel<0><<<dim3(1, cdiv(n, 64)), TB>>>((const __half*)pX16, (const __half*)pW1h,
                                                  (__half*)pBufA, n, 64, 128, nullptr, nullptr);

    // ===== Join, then layer 1: GCNConv(128 -> 64) + relu (fused) =====
    cudaStreamWaitEvent(0, g_side.join, 0);
    gcn_gather_kernel<<<cdiv((long long)n * 32, TB), TB>>>(b1, n);

    // ===== Layer 2: GATConv(64 -> 64, heads=2, concat) + relu =====
    hgemm_kernel<2><<<dim3(2, cdiv(n, 64)), TB>>>((const __half*)pBufB, (const __half*)pW2h,
                                                  (__half*)pBufA, n, 128, 64, as2, ad2);
    gat_gather_kernel<2, 64, true><<<cdiv((long long)n * 32, TB), TB>>>(b2, n, (__half*)pBufB);

    // ===== Layer 3: GATConv(128 -> 64, heads=1, mean) =====
    hgemm_kernel<1><<<dim3(1, cdiv(n, 64)), TB>>>((const __half*)pBufB, (const __half*)pW3h,
                                                  (__half*)pBufA, n, 64, 128, as3, ad3);
    gat_gather_kernel<1, 64, false><<<cdiv((long long)n * 32, TB), TB>>>(b3, n, (__half*)pBufB);

    // ===== Mean pool + FC + log_softmax =====
    pool_kernel<<<cdiv((long long)n * 16, TB), TB>>>(bat, n);
    final_kernel<<<cdiv(G, TB), TB>>>(Wfc, bfc, (float*)d_out, G);
}